// round 2
// baseline (speedup 1.0000x reference)
#include <cuda_runtime.h>
#include <math.h>

#define SD   2048          // sequence length
#define HD   2048          // hidden
#define BN   4             // batch
#define RK   32            // attention rank
#define MH   128           // mlp hidden
#define NOUT 100           // digits*classes

// ---------------- scratch (device globals; no runtime allocation) ----------------
__device__ float g_Wcat[128 * HD];                         // 1 MB  [Qa|Ka|Qb|Kb] rows
__device__ float g_proj[BN * SD * 128];                    // 4 MB  [b][s][128]
__device__ float g_P[33554432];                            // 134 MB [z=branch*4+batch][s][t]
__device__ float g_hattn[33554432];                        // 134 MB [z][s][h]
__device__ float g_y1[2 * BN * SD * MH];                   // 8 MB  [branch][b*s][128]

// ---------------- pack the 4 low-rank W matrices into one [128, HD] ----------------
__global__ void pack_w_kernel(const float* __restrict__ qa, const float* __restrict__ ka,
                              const float* __restrict__ qb, const float* __restrict__ kb,
                              float* __restrict__ wcat)
{
    int i = blockIdx.x * 256 + threadIdx.x;          // 0 .. 65535 (= 32*2048)
    if (i < RK * HD) {
        wcat[i]              = qa[i];
        wcat[RK * HD + i]    = ka[i];
        wcat[2 * RK * HD + i] = qb[i];
        wcat[3 * RK * HD + i] = kb[i];
    }
}

// ---------------- generic 128x128x8 SGEMM, 256 thr, 8x8 micro-tile ----------------
// C[M,N] = A[M,K] * op(B);  BNT: B is [N,K] row-major (C=A*B^T), else B is [K,N].
// CAUSAL: only accumulate k < bm+128 (rows of A beyond that are zero / unread).
// GELU: C = gelu(acc + bias[n]) (exact erf gelu).
template<bool BNT, bool CAUSAL, bool GELU>
__global__ void __launch_bounds__(256, 2) gemm_kernel(
    const float* __restrict__ Ag, const float* __restrict__ Bg,
    const float* __restrict__ bias, float* __restrict__ Cg,
    int M, int N, int K, long aZ, long bZ, int bMod, long cZ)
{
    int z = blockIdx.z;
    const float* A = Ag + (size_t)z * (size_t)aZ;
    const float* B = Bg + (size_t)(z % bMod) * (size_t)bZ;
    float*       C = Cg + (size_t)z * (size_t)cZ;

    int bm = blockIdx.y * 128, bn = blockIdx.x * 128;
    int kEnd = CAUSAL ? ((bm + 128 < K) ? bm + 128 : K) : K;

    __shared__ float As[8][128];
    __shared__ float Bs[8][128];

    int tid = threadIdx.x;
    int tx = tid & 15, ty = tid >> 4;

    float acc[8][8];
    #pragma unroll
    for (int i = 0; i < 8; i++)
        #pragma unroll
        for (int j = 0; j < 8; j++) acc[i][j] = 0.f;

    int aRow = tid >> 1, aK = (tid & 1) * 4;

    for (int k0 = 0; k0 < kEnd; k0 += 8) {
        float4 av = *reinterpret_cast<const float4*>(&A[(size_t)(bm + aRow) * K + k0 + aK]);
        As[aK + 0][aRow] = av.x; As[aK + 1][aRow] = av.y;
        As[aK + 2][aRow] = av.z; As[aK + 3][aRow] = av.w;
        if (BNT) {
            int n = tid >> 1, kc = (tid & 1) * 4;
            float4 bv = *reinterpret_cast<const float4*>(&B[(size_t)(bn + n) * K + k0 + kc]);
            Bs[kc + 0][n] = bv.x; Bs[kc + 1][n] = bv.y;
            Bs[kc + 2][n] = bv.z; Bs[kc + 3][n] = bv.w;
        } else {
            int kr = tid >> 5, c = (tid & 31) * 4;
            *reinterpret_cast<float4*>(&Bs[kr][c]) =
                *reinterpret_cast<const float4*>(&B[(size_t)(k0 + kr) * N + bn + c]);
        }
        __syncthreads();
        #pragma unroll
        for (int kk = 0; kk < 8; kk++) {
            float a[8], b[8];
            *reinterpret_cast<float4*>(&a[0]) = *reinterpret_cast<const float4*>(&As[kk][ty * 8]);
            *reinterpret_cast<float4*>(&a[4]) = *reinterpret_cast<const float4*>(&As[kk][ty * 8 + 4]);
            *reinterpret_cast<float4*>(&b[0]) = *reinterpret_cast<const float4*>(&Bs[kk][tx * 8]);
            *reinterpret_cast<float4*>(&b[4]) = *reinterpret_cast<const float4*>(&Bs[kk][tx * 8 + 4]);
            #pragma unroll
            for (int i = 0; i < 8; i++)
                #pragma unroll
                for (int j = 0; j < 8; j++) acc[i][j] += a[i] * b[j];
        }
        __syncthreads();
    }

    #pragma unroll
    for (int i = 0; i < 8; i++) {
        int row = bm + ty * 8 + i;
        #pragma unroll
        for (int jj = 0; jj < 2; jj++) {
            float4 v;
            float* vv = reinterpret_cast<float*>(&v);
            #pragma unroll
            for (int u = 0; u < 4; u++) {
                int j = jj * 4 + u;
                float x = acc[i][j];
                if (GELU) {
                    x += bias[bn + tx * 8 + j];
                    x = 0.5f * x * (1.f + erff(x * 0.7071067811865476f));
                }
                vv[u] = x;
            }
            *reinterpret_cast<float4*>(&C[(size_t)row * N + bn + tx * 8 + jj * 4]) = v;
        }
    }
}

// ---------------- fused attention scores + softmax: writes normalized P ----------------
// grid: (S/64, 1, 8) z = branch*4+batch; block 256.
// Thread owns one query row (s = tid&63), covers keys t = (tid>>6)*32 + j.
__global__ void __launch_bounds__(256) attn_scores_kernel(
    const float* __restrict__ proj, const int* __restrict__ mask, float* __restrict__ P)
{
    int z = blockIdx.z;
    int branch = z >> 2, batch = z & 3;
    int s0 = blockIdx.x * 64;
    int tid = threadIdx.x;
    int sLoc = tid & 63, cg = tid >> 6;
    int sG = s0 + sLoc;

    __shared__ float Ks[128][32];
    __shared__ float pm[4][64], pl[4][64];
    __shared__ float Mrow[64], Linv[64];
    __shared__ int   msk[128];

    const float scale = 0.17677669529663689f;   // 1/sqrt(32)

    // Q row into registers (proj row layout: [Qa(32)|Ka(32)|Qb(32)|Kb(32)])
    float q[32];
    const float* qrow = proj + ((size_t)(batch * SD + sG)) * 128 + branch * 64;
    #pragma unroll
    for (int r4 = 0; r4 < 8; r4++) {
        float4 v = *reinterpret_cast<const float4*>(qrow + r4 * 4);
        q[r4 * 4 + 0] = v.x; q[r4 * 4 + 1] = v.y; q[r4 * 4 + 2] = v.z; q[r4 * 4 + 3] = v.w;
    }
    int kOff = branch * 64 + 32;
    int tLim = ((s0 >> 7) + 1) << 7;            // key range the PV GEMM will read
    if (tLim > SD) tLim = SD;

    // pass 1: online max / sum
    float m = -INFINITY, l = 0.f;
    for (int t0 = 0; t0 < tLim; t0 += 128) {
        for (int i = tid; i < 128 * 8; i += 256) {
            int t = i >> 3, r4 = i & 7;
            *reinterpret_cast<float4*>(&Ks[t][r4 * 4]) =
                *reinterpret_cast<const float4*>(proj + ((size_t)(batch * SD + t0 + t)) * 128 + kOff + r4 * 4);
        }
        if (tid < 128) msk[tid] = mask[batch * SD + t0 + tid];
        __syncthreads();
        #pragma unroll 4
        for (int j = 0; j < 32; j++) {
            int tl = cg * 32 + j;
            int tG = t0 + tl;
            float x;
            if (tG > sG || msk[tl] == 0) x = -1e9f;
            else {
                float d = 0.f;
                #pragma unroll
                for (int r = 0; r < 32; r++) d += q[r] * Ks[tl][r];
                x = d * scale;
            }
            if (x > m) { l = l * __expf(m - x) + 1.f; m = x; }
            else       { l += __expf(x - m); }
        }
        __syncthreads();
    }
    pm[cg][sLoc] = m; pl[cg][sLoc] = l;
    __syncthreads();
    if (tid < 64) {
        float M = pm[0][tid];
        #pragma unroll
        for (int c = 1; c < 4; c++) M = fmaxf(M, pm[c][tid]);
        float L = 0.f;
        #pragma unroll
        for (int c = 0; c < 4; c++) L += pl[c][tid] * __expf(pm[c][tid] - M);
        Mrow[tid] = M; Linv[tid] = 1.f / L;
    }
    __syncthreads();
    float Mr = Mrow[sLoc], Li = Linv[sLoc];

    // pass 2: write normalized probabilities (float4 per thread)
    float* Prow = P + ((size_t)z * SD + sG) * SD;
    for (int t0 = 0; t0 < tLim; t0 += 128) {
        for (int i = tid; i < 128 * 8; i += 256) {
            int t = i >> 3, r4 = i & 7;
            *reinterpret_cast<float4*>(&Ks[t][r4 * 4]) =
                *reinterpret_cast<const float4*>(proj + ((size_t)(batch * SD + t0 + t)) * 128 + kOff + r4 * 4);
        }
        if (tid < 128) msk[tid] = mask[batch * SD + t0 + tid];
        __syncthreads();
        #pragma unroll
        for (int j4 = 0; j4 < 8; j4++) {
            float4 pv;
            float* pp = reinterpret_cast<float*>(&pv);
            #pragma unroll
            for (int u = 0; u < 4; u++) {
                int tl = cg * 32 + j4 * 4 + u;
                int tG = t0 + tl;
                float x;
                if (tG > sG || msk[tl] == 0) x = -1e9f;
                else {
                    float d = 0.f;
                    #pragma unroll
                    for (int r = 0; r < 32; r++) d += q[r] * Ks[tl][r];
                    x = d * scale;
                }
                pp[u] = __expf(x - Mr) * Li;
            }
            *reinterpret_cast<float4*>(&Prow[t0 + cg * 32 + j4 * 4]) = pv;
        }
        __syncthreads();
    }
}

// ---------------- head: logits = y1 @ W2^T + b2, warp per row, split outputs ----------------
// grid (2048, 2): blockIdx.y selects outputs [oHalf*50, oHalf*50+50)
__global__ void __launch_bounds__(256) head_kernel(
    const float* __restrict__ y1,
    const float* __restrict__ W2a, const float* __restrict__ b2a,
    const float* __restrict__ W2b, const float* __restrict__ b2b,
    float* __restrict__ out)
{
    int tid = threadIdx.x;
    int rowBase = blockIdx.x * 8;                 // 0 .. 16376
    int oHalf = blockIdx.y;
    int branch = rowBase >> 13;
    const float* W2 = branch ? W2b : W2a;
    const float* b2 = branch ? b2b : b2a;

    __shared__ float W2s[128][52];                // [k][o-local]
    for (int i = tid; i < 128 * 50; i += 256) {
        int k = i / 50, o = i % 50;
        W2s[k][o] = W2[(size_t)(oHalf * 50 + o) * 128 + k];
    }
    __syncthreads();

    int warp = tid >> 5, lane = tid & 31;
    int row = rowBase + warp;
    int bs = row & 8191;
    const float* yrow = y1 + (size_t)row * 128;
    float y[4];
    #pragma unroll
    for (int u = 0; u < 4; u++) y[u] = yrow[lane + u * 32];

    int o0 = lane * 2;
    bool active = (o0 < 50);
    float acc0 = 0.f, acc1 = 0.f;
    #pragma unroll 4
    for (int k = 0; k < 128; k++) {
        float yv = __shfl_sync(0xffffffffu, y[k >> 5], k & 31);
        if (active) {
            acc0 += yv * W2s[k][o0];
            acc1 += yv * W2s[k][o0 + 1];
        }
    }
    if (active) {
        int og = oHalf * 50;
        float* lo = out + 163840 + (size_t)branch * 819200 + (size_t)bs * 100 + og;
        lo[o0]     = acc0 + b2[og + o0];
        lo[o0 + 1] = acc1 + b2[og + o0 + 1];
    }
}

// ---------------- STE argmax over each digit group of 10 logits ----------------
__global__ void ste_kernel(float* __restrict__ out)
{
    int idx = blockIdx.x * blockDim.x + threadIdx.x;     // 0 .. 163839
    if (idx >= 2 * BN * SD * 10) return;
    int dg = idx % 10;
    int row = idx / 10;
    int branch = row >> 13, bs = row & 8191;
    const float* lg = out + 163840 + (size_t)branch * 819200 + (size_t)bs * 100 + dg * 10;
    float v[10];
    #pragma unroll
    for (int j = 0; j < 10; j++) v[j] = lg[j];
    float mx = v[0]; int am = 0;
    #pragma unroll
    for (int j = 1; j < 10; j++) if (v[j] > mx) { mx = v[j]; am = j; }
    float se = 0.f, sw = 0.f;
    #pragma unroll
    for (int j = 0; j < 10; j++) {
        float e = __expf(v[j] - mx);
        se += e; sw += e * (float)j;
    }
    float soft = sw / se;
    float hard = (float)am;
    out[(size_t)branch * 81920 + (size_t)bs * 10 + dg] = soft + (hard - soft);
}

// ---------------- launch ----------------
extern "C" void kernel_launch(void* const* d_in, const int* in_sizes, int n_in,
                              void* d_out, int out_size)
{
    const float* h    = (const float*)d_in[0];
    const int*   mask = (const int*)  d_in[1];
    const float* Wq_a = (const float*)d_in[2];
    const float* Wk_a = (const float*)d_in[3];
    const float* Wq_b = (const float*)d_in[4];
    const float* Wk_b = (const float*)d_in[5];
    const float* W1_a = (const float*)d_in[6];
    const float* b1_a = (const float*)d_in[7];
    const float* W2_a = (const float*)d_in[8];
    const float* b2_a = (const float*)d_in[9];
    const float* W1_b = (const float*)d_in[10];
    const float* b1_b = (const float*)d_in[11];
    const float* W2_b = (const float*)d_in[12];
    const float* b2_b = (const float*)d_in[13];
    float* out = (float*)d_out;

    float *wcat, *proj, *P, *hattn, *y1;
    cudaGetSymbolAddress((void**)&wcat,  g_Wcat);
    cudaGetSymbolAddress((void**)&proj,  g_proj);
    cudaGetSymbolAddress((void**)&P,     g_P);
    cudaGetSymbolAddress((void**)&hattn, g_hattn);
    cudaGetSymbolAddress((void**)&y1,    g_y1);

    // 1) pack W -> [128, HD]
    pack_w_kernel<<<256, 256>>>(Wq_a, Wk_a, Wq_b, Wk_b, wcat);

    // 2) projections: [8192,2048] x [128,2048]^T -> [8192,128]
    gemm_kernel<true, false, false><<<dim3(1, 64, 1), 256>>>(
        h, wcat, nullptr, proj, BN * SD, 128, HD, 0, 0, 1, 0);

    // 3) scores + softmax -> P  (normalized, causal+pad masked)
    attn_scores_kernel<<<dim3(SD / 64, 1, 8), 256>>>(proj, mask, P);

    // 4) h_attn = P @ h   (batched over z = branch*4+batch, causal k-skip)
    gemm_kernel<false, true, false><<<dim3(16, 16, 8), 256>>>(
        P, h, nullptr, hattn, SD, HD, SD,
        (long)SD * SD, (long)SD * HD, 4, (long)SD * HD);

    // 5) y1 = gelu(h_attn @ W1^T + b1) per branch
    gemm_kernel<true, false, true><<<dim3(1, 64, 1), 256>>>(
        hattn, W1_a, b1_a, y1, BN * SD, MH, HD, 0, 0, 1, 0);
    gemm_kernel<true, false, true><<<dim3(1, 64, 1), 256>>>(
        hattn + (size_t)BN * SD * HD, W1_b, b1_b, y1 + (size_t)BN * SD * MH,
        BN * SD, MH, HD, 0, 0, 1, 0);

    // 6) logits = y1 @ W2^T + b2  (written straight into d_out)
    head_kernel<<<dim3(2048, 2), 256>>>(y1, W2_a, b2_a, W2_b, b2_b, out);

    // 7) STE argmax digits
    ste_kernel<<<(2 * BN * SD * 10 + 255) / 256, 256>>>(out);
}

// round 7
// speedup vs baseline: 2.8877x; 2.8877x over previous
#include <cuda_runtime.h>
#include <math.h>
#include <stdint.h>

#define SD   2048          // sequence length
#define HD   2048          // hidden
#define BN   4             // batch
#define RK   32            // attention rank
#define MH   128           // mlp hidden
#define NW   384           // packed weight rows: Qa|Ka|Qb|Kb|W1a|W1b

// ---------------- scratch (device globals; no runtime allocation) ----------------
__device__ float g_Wcat[NW * HD];                          // 3 MB
__device__ float g_projM[BN * SD * NW];                    // 12.6 MB [b][s][384]
__device__ float g_P[33554432];                            // 134 MB [z][s][t] unnormalized exp
__device__ float g_Linv[8 * SD];                           // row 1/sum
__device__ float g_y1[2 * BN * SD * MH];                   // 8 MB [branch][b*s][128]

// ---------------- pack all weights into one [384, HD] ----------------
__global__ void pack_w_kernel(const float* __restrict__ qa, const float* __restrict__ ka,
                              const float* __restrict__ qb, const float* __restrict__ kb,
                              const float* __restrict__ w1a, const float* __restrict__ w1b,
                              float* __restrict__ wcat)
{
    int i = blockIdx.x * 256 + threadIdx.x;          // 0 .. 786431
    if (i >= NW * HD) return;
    if      (i <  65536) wcat[i] = qa[i];
    else if (i < 131072) wcat[i] = ka[i -  65536];
    else if (i < 196608) wcat[i] = qb[i - 131072];
    else if (i < 262144) wcat[i] = kb[i - 196608];
    else if (i < 524288) wcat[i] = w1a[i - 262144];
    else                 wcat[i] = w1b[i - 524288];
}

// ---------------- 128x128x8 SGEMM, C = A * B^T (A [M,K], B [N,K] row-major) ----------------
__global__ void __launch_bounds__(256, 2) gemm_nt_kernel(
    const float* __restrict__ A, const float* __restrict__ B, float* __restrict__ C,
    int M, int N, int K)
{
    int bm = blockIdx.y * 128, bn = blockIdx.x * 128;

    __shared__ float As[8][128];
    __shared__ float Bs[8][128];

    int tid = threadIdx.x;
    int tx = tid & 15, ty = tid >> 4;

    float acc[8][8];
    #pragma unroll
    for (int i = 0; i < 8; i++)
        #pragma unroll
        for (int j = 0; j < 8; j++) acc[i][j] = 0.f;

    int aRow = tid >> 1, aK = (tid & 1) * 4;

    for (int k0 = 0; k0 < K; k0 += 8) {
        float4 av = *reinterpret_cast<const float4*>(&A[(size_t)(bm + aRow) * K + k0 + aK]);
        As[aK + 0][aRow] = av.x; As[aK + 1][aRow] = av.y;
        As[aK + 2][aRow] = av.z; As[aK + 3][aRow] = av.w;
        float4 bv = *reinterpret_cast<const float4*>(&B[(size_t)(bn + aRow) * K + k0 + aK]);
        Bs[aK + 0][aRow] = bv.x; Bs[aK + 1][aRow] = bv.y;
        Bs[aK + 2][aRow] = bv.z; Bs[aK + 3][aRow] = bv.w;
        __syncthreads();
        #pragma unroll
        for (int kk = 0; kk < 8; kk++) {
            float a[8], b[8];
            *reinterpret_cast<float4*>(&a[0]) = *reinterpret_cast<const float4*>(&As[kk][ty * 8]);
            *reinterpret_cast<float4*>(&a[4]) = *reinterpret_cast<const float4*>(&As[kk][ty * 8 + 4]);
            *reinterpret_cast<float4*>(&b[0]) = *reinterpret_cast<const float4*>(&Bs[kk][tx * 8]);
            *reinterpret_cast<float4*>(&b[4]) = *reinterpret_cast<const float4*>(&Bs[kk][tx * 8 + 4]);
            #pragma unroll
            for (int i = 0; i < 8; i++)
                #pragma unroll
                for (int j = 0; j < 8; j++) acc[i][j] += a[i] * b[j];
        }
        __syncthreads();
    }

    #pragma unroll
    for (int i = 0; i < 8; i++) {
        int row = bm + ty * 8 + i;
        #pragma unroll
        for (int jj = 0; jj < 2; jj++) {
            float4 v;
            float* vv = reinterpret_cast<float*>(&v);
            #pragma unroll
            for (int u = 0; u < 4; u++) vv[u] = acc[i][jj * 4 + u];
            *reinterpret_cast<float4*>(&C[(size_t)row * N + bn + tx * 8 + jj * 4]) = v;
        }
    }
}

// ---------------- single-pass scores: P = exp(QK^T*scale) (masked), Linv = 1/rowsum ----------------
// grid (32, 1, 8), block 256. 64 queries per block; cg = tid>>6 covers key quarter.
__global__ void __launch_bounds__(256) attn_scores1p_kernel(
    const float* __restrict__ projM, const int* __restrict__ mask,
    float* __restrict__ P, float* __restrict__ Linv)
{
    int z = blockIdx.z;
    int branch = z >> 2, batch = z & 3;
    int s0 = blockIdx.x * 64;
    int tid = threadIdx.x;
    int sLoc = tid & 63, cg = tid >> 6;
    int sG = s0 + sLoc;

    __shared__ float Ks[128][32];
    __shared__ float pl[4][64];
    __shared__ int   msk[128];

    const float scale = 0.17677669529663689f;   // 1/sqrt(32)

    // Q row into registers
    float q[32];
    const float* qrow = projM + ((size_t)(batch * SD + sG)) * NW + branch * 64;
    #pragma unroll
    for (int r4 = 0; r4 < 8; r4++) {
        float4 v = *reinterpret_cast<const float4*>(qrow + r4 * 4);
        q[r4 * 4 + 0] = v.x; q[r4 * 4 + 1] = v.y; q[r4 * 4 + 2] = v.z; q[r4 * 4 + 3] = v.w;
    }
    int kOff = branch * 64 + 32;
    int tLim = ((s0 >> 7) + 1) << 7;            // key range the PV GEMM will read
    if (tLim > SD) tLim = SD;

    float l = 0.f;
    float* Prow = P + ((size_t)z * SD + sG) * SD;
    for (int t0 = 0; t0 < tLim; t0 += 128) {
        for (int i = tid; i < 128 * 8; i += 256) {
            int t = i >> 3, r4 = i & 7;
            *reinterpret_cast<float4*>(&Ks[t][r4 * 4]) =
                *reinterpret_cast<const float4*>(projM + ((size_t)(batch * SD + t0 + t)) * NW + kOff + r4 * 4);
        }
        if (tid < 128) msk[tid] = mask[batch * SD + t0 + tid];
        __syncthreads();
        #pragma unroll
        for (int j4 = 0; j4 < 8; j4++) {
            float4 pv;
            float* pp = reinterpret_cast<float*>(&pv);
            #pragma unroll
            for (int u = 0; u < 4; u++) {
                int tl = cg * 32 + j4 * 4 + u;
                int tG = t0 + tl;
                float e;
                if (tG > sG || msk[tl] == 0) e = 0.f;
                else {
                    float d = 0.f;
                    #pragma unroll
                    for (int r = 0; r < 32; r++) d += q[r] * Ks[tl][r];
                    e = __expf(d * scale);
                }
                l += e;
                pp[u] = e;
            }
            *reinterpret_cast<float4*>(&Prow[t0 + cg * 32 + j4 * 4]) = pv;
        }
        __syncthreads();
    }
    pl[cg][sLoc] = l;
    __syncthreads();
    if (tid < 64) {
        float L = pl[0][tid] + pl[1][tid] + pl[2][tid] + pl[3][tid];
        Linv[(size_t)z * SD + s0 + tid] = 1.f / fmaxf(L, 1e-30f);
    }
}

// ---------------- PV fused MLP1: y1 = gelu((P @ M) * Linv + b1) ----------------
// grid (1, 16, 8), block 256. A = P[z] [2048 x kEnd]; B = M cols of projM [k][128].
__global__ void __launch_bounds__(256, 2) pv_gelu_kernel(
    const float* __restrict__ P, const float* __restrict__ projM,
    const float* __restrict__ Linv,
    const float* __restrict__ b1a, const float* __restrict__ b1b,
    float* __restrict__ y1)
{
    int z = blockIdx.z;
    int branch = z >> 2, batch = z & 3;
    int bm = blockIdx.y * 128;
    int kEnd = bm + 128; if (kEnd > SD) kEnd = SD;
    const float* A = P + (size_t)z * SD * SD;
    const float* B = projM + (size_t)batch * SD * NW + 128 + branch * 128;
    const float* b1 = branch ? b1b : b1a;

    __shared__ float As[8][128];
    __shared__ float Bs[8][128];
    __shared__ float Ls[128];

    int tid = threadIdx.x;
    int tx = tid & 15, ty = tid >> 4;

    float acc[8][8];
    #pragma unroll
    for (int i = 0; i < 8; i++)
        #pragma unroll
        for (int j = 0; j < 8; j++) acc[i][j] = 0.f;

    int aRow = tid >> 1, aK = (tid & 1) * 4;
    int bKr = tid >> 5, bC = (tid & 31) * 4;

    for (int k0 = 0; k0 < kEnd; k0 += 8) {
        float4 av = *reinterpret_cast<const float4*>(&A[(size_t)(bm + aRow) * SD + k0 + aK]);
        As[aK + 0][aRow] = av.x; As[aK + 1][aRow] = av.y;
        As[aK + 2][aRow] = av.z; As[aK + 3][aRow] = av.w;
        *reinterpret_cast<float4*>(&Bs[bKr][bC]) =
            *reinterpret_cast<const float4*>(&B[(size_t)(k0 + bKr) * NW + bC]);
        __syncthreads();
        #pragma unroll
        for (int kk = 0; kk < 8; kk++) {
            float a[8], b[8];
            *reinterpret_cast<float4*>(&a[0]) = *reinterpret_cast<const float4*>(&As[kk][ty * 8]);
            *reinterpret_cast<float4*>(&a[4]) = *reinterpret_cast<const float4*>(&As[kk][ty * 8 + 4]);
            *reinterpret_cast<float4*>(&b[0]) = *reinterpret_cast<const float4*>(&Bs[kk][tx * 8]);
            *reinterpret_cast<float4*>(&b[4]) = *reinterpret_cast<const float4*>(&Bs[kk][tx * 8 + 4]);
            #pragma unroll
            for (int i = 0; i < 8; i++)
                #pragma unroll
                for (int j = 0; j < 8; j++) acc[i][j] += a[i] * b[j];
        }
        __syncthreads();
    }

    if (tid < 128) Ls[tid] = Linv[(size_t)z * SD + bm + tid];
    __syncthreads();

    #pragma unroll
    for (int i = 0; i < 8; i++) {
        int rloc = ty * 8 + i;
        float li = Ls[rloc];
        int row = bm + rloc;
        #pragma unroll
        for (int jj = 0; jj < 2; jj++) {
            float4 v;
            float* vv = reinterpret_cast<float*>(&v);
            #pragma unroll
            for (int u = 0; u < 4; u++) {
                int j = jj * 4 + u;
                float x = acc[i][j] * li + b1[tx * 8 + j];
                vv[u] = 0.5f * x * (1.f + erff(x * 0.7071067811865476f));
            }
            *reinterpret_cast<float4*>(&y1[((size_t)z * SD + row) * MH + tx * 8 + jj * 4]) = v;
        }
    }
}

// ---------------- head: logits = y1 @ W2^T + b2 ----------------
__global__ void __launch_bounds__(256) head_kernel(
    const float* __restrict__ y1,
    const float* __restrict__ W2a, const float* __restrict__ b2a,
    const float* __restrict__ W2b, const float* __restrict__ b2b,
    float* __restrict__ out)
{
    int tid = threadIdx.x;
    int rowBase = blockIdx.x * 8;
    int oHalf = blockIdx.y;
    int branch = rowBase >> 13;
    const float* W2 = branch ? W2b : W2a;
    const float* b2 = branch ? b2b : b2a;

    __shared__ float W2s[128][52];
    for (int i = tid; i < 128 * 50; i += 256) {
        int k = i / 50, o = i % 50;
        W2s[k][o] = W2[(size_t)(oHalf * 50 + o) * 128 + k];
    }
    __syncthreads();

    int warp = tid >> 5, lane = tid & 31;
    int row = rowBase + warp;
    int bs = row & 8191;
    const float* yrow = y1 + (size_t)row * 128;
    float y[4];
    #pragma unroll
    for (int u = 0; u < 4; u++) y[u] = yrow[lane + u * 32];

    int o0 = lane * 2;
    bool active = (o0 < 50);
    float acc0 = 0.f, acc1 = 0.f;
    #pragma unroll 4
    for (int k = 0; k < 128; k++) {
        float yv = __shfl_sync(0xffffffffu, y[k >> 5], k & 31);
        if (active) {
            acc0 += yv * W2s[k][o0];
            acc1 += yv * W2s[k][o0 + 1];
        }
    }
    if (active) {
        int og = oHalf * 50;
        float* lo = out + 163840 + (size_t)branch * 819200 + (size_t)bs * 100 + og;
        lo[o0]     = acc0 + b2[og + o0];
        lo[o0 + 1] = acc1 + b2[og + o0 + 1];
    }
}

// ---------------- STE argmax ----------------
__global__ void ste_kernel(float* __restrict__ out)
{
    int idx = blockIdx.x * blockDim.x + threadIdx.x;
    if (idx >= 2 * BN * SD * 10) return;
    int dg = idx % 10;
    int row = idx / 10;
    int branch = row >> 13, bs = row & 8191;
    const float* lg = out + 163840 + (size_t)branch * 819200 + (size_t)bs * 100 + dg * 10;
    float v[10];
    #pragma unroll
    for (int j = 0; j < 10; j++) v[j] = lg[j];
    float mx = v[0]; int am = 0;
    #pragma unroll
    for (int j = 1; j < 10; j++) if (v[j] > mx) { mx = v[j]; am = j; }
    float se = 0.f, sw = 0.f;
    #pragma unroll
    for (int j = 0; j < 10; j++) {
        float e = __expf(v[j] - mx);
        se += e; sw += e * (float)j;
    }
    float soft = sw / se;
    float hard = (float)am;
    out[(size_t)branch * 81920 + (size_t)bs * 10 + dg] = soft + (hard - soft);
}

// ---------------- launch ----------------
extern "C" void kernel_launch(void* const* d_in, const int* in_sizes, int n_in,
                              void* d_out, int out_size)
{
    const float* h    = (const float*)d_in[0];
    const int*   mask = (const int*)  d_in[1];
    const float* Wq_a = (const float*)d_in[2];
    const float* Wk_a = (const float*)d_in[3];
    const float* Wq_b = (const float*)d_in[4];
    const float* Wk_b = (const float*)d_in[5];
    const float* W1_a = (const float*)d_in[6];
    const float* b1_a = (const float*)d_in[7];
    const float* W2_a = (const float*)d_in[8];
    const float* b2_a = (const float*)d_in[9];
    const float* W1_b = (const float*)d_in[10];
    const float* b1_b = (const float*)d_in[11];
    const float* W2_b = (const float*)d_in[12];
    const float* b2_b = (const float*)d_in[13];
    float* out = (float*)d_out;

    float *wcat, *projM, *P, *Linv, *y1;
    cudaGetSymbolAddress((void**)&wcat,  g_Wcat);
    cudaGetSymbolAddress((void**)&projM, g_projM);
    cudaGetSymbolAddress((void**)&P,     g_P);
    cudaGetSymbolAddress((void**)&Linv,  g_Linv);
    cudaGetSymbolAddress((void**)&y1,    g_y1);

    // 1) pack [Qa|Ka|Qb|Kb|W1a|W1b] -> [384, 2048]
    pack_w_kernel<<<(NW * HD + 255) / 256, 256>>>(Wq_a, Wk_a, Wq_b, Wk_b, W1_a, W1_b, wcat);

    // 2) projM = h @ Wcat^T : [8192, 384] (Q,K and M_a = h W1a^T, M_b = h W1b^T)
    gemm_nt_kernel<<<dim3(3, 64, 1), 256>>>(h, wcat, projM, BN * SD, NW, HD);

    // 3) single-pass scores: P = exp(QK^T scale) masked (unnormalized), Linv
    attn_scores1p_kernel<<<dim3(SD / 64, 1, 8), 256>>>(projM, mask, P, Linv);

    // 4) y1 = gelu((P @ M) * Linv + b1)   (causal k-skip, N=128)
    pv_gelu_kernel<<<dim3(1, 16, 8), 256>>>(P, projM, Linv, b1_a, b1_b, y1);

    // 5) logits -> d_out
    head_kernel<<<dim3(2048, 2), 256>>>(y1, W2_a, b2_a, W2_b, b2_b, out);

    // 6) STE argmax digits
    ste_kernel<<<(2 * BN * SD * 10 + 255) / 256, 256>>>(out);
}